// round 1
// baseline (speedup 1.0000x reference)
#include <cuda_runtime.h>
#include <math.h>

// ---------------------------------------------------------------------------
// Problem constants
// ---------------------------------------------------------------------------
#define BATCH 4
#define SEQ   4096
#define DMODEL 2048
#define HD    128          // head dim per sub-head
#define DV    256          // 2*HD = value dim = qkv proj width
#define MROWS (BATCH*SEQ)  // 16384

// Scratch for projected Q,K,V (each [B*S, 256] fp32 = 16 MB)
__device__ float g_Q[MROWS * DV];
__device__ float g_K[MROWS * DV];
__device__ float g_V[MROWS * DV];

// ---------------------------------------------------------------------------
// Kernel 1: fused projection GEMM.
// C = x @ W, x:[16384,2048] row-major, W:[2048,256] row-major.
// blockIdx.z selects (WQ->g_Q, WK->g_K, WV->g_V).
// Tiling: BM=128, BN=128, BK=16, 256 threads, 8x8 per thread.
// ---------------------------------------------------------------------------
__global__ __launch_bounds__(256) void proj_gemm_kernel(
    const float* __restrict__ x,
    const float* __restrict__ WQ,
    const float* __restrict__ WK,
    const float* __restrict__ WV)
{
    const int BM = 128, BN = 128, BK = 16;
    const int K = DMODEL, N = DV;

    const float* __restrict__ B =
        (blockIdx.z == 0) ? WQ : (blockIdx.z == 1) ? WK : WV;
    float* __restrict__ C =
        (blockIdx.z == 0) ? g_Q : (blockIdx.z == 1) ? g_K : g_V;

    __shared__ float As[BK][BM];   // A stored transposed: As[k][m]
    __shared__ float Bs[BK][BN];

    const int tid  = threadIdx.x;
    const int brow = blockIdx.y * BM;
    const int bcol = blockIdx.x * BN;

    // A tile loads: 128 rows x 16 cols, float4 per thread, 2 row-passes of 64
    const int rowA = tid >> 2;          // 0..63
    const int colA = (tid & 3) * 4;     // 0,4,8,12
    // B tile loads: 16 rows x 128 cols, float4 per thread, 2 row-passes of 8
    const int rowB = tid >> 5;          // 0..7
    const int colB = (tid & 31) * 4;    // 0..124

    const int tr = (tid / 16) * 8;      // output row offset within tile
    const int tc = (tid % 16) * 8;      // output col offset within tile

    float acc[8][8];
#pragma unroll
    for (int i = 0; i < 8; i++)
#pragma unroll
        for (int j = 0; j < 8; j++) acc[i][j] = 0.f;

    for (int k0 = 0; k0 < K; k0 += BK) {
        // stage A
#pragma unroll
        for (int p = 0; p < 2; p++) {
            float4 v = *(const float4*)&x[(size_t)(brow + rowA + p * 64) * K + k0 + colA];
            As[colA + 0][rowA + p * 64] = v.x;
            As[colA + 1][rowA + p * 64] = v.y;
            As[colA + 2][rowA + p * 64] = v.z;
            As[colA + 3][rowA + p * 64] = v.w;
        }
        // stage B
#pragma unroll
        for (int p = 0; p < 2; p++) {
            float4 v = *(const float4*)&B[(size_t)(k0 + rowB + p * 8) * N + bcol + colB];
            *(float4*)&Bs[rowB + p * 8][colB] = v;
        }
        __syncthreads();

#pragma unroll
        for (int k = 0; k < BK; k++) {
            float4 a0 = *(const float4*)&As[k][tr];
            float4 a1 = *(const float4*)&As[k][tr + 4];
            float4 b0 = *(const float4*)&Bs[k][tc];
            float4 b1 = *(const float4*)&Bs[k][tc + 4];
            float ra[8] = {a0.x, a0.y, a0.z, a0.w, a1.x, a1.y, a1.z, a1.w};
            float rb[8] = {b0.x, b0.y, b0.z, b0.w, b1.x, b1.y, b1.z, b1.w};
#pragma unroll
            for (int i = 0; i < 8; i++)
#pragma unroll
                for (int j = 0; j < 8; j++) acc[i][j] += ra[i] * rb[j];
        }
        __syncthreads();
    }

#pragma unroll
    for (int i = 0; i < 8; i++) {
#pragma unroll
        for (int j = 0; j < 8; j += 4) {
            float4 v = make_float4(acc[i][j], acc[i][j + 1], acc[i][j + 2], acc[i][j + 3]);
            *(float4*)&C[(size_t)(brow + tr + i) * N + bcol + tc + j] = v;
        }
    }
}

// ---------------------------------------------------------------------------
// Kernel 2: flash-style differential attention.
// Per CTA: BM=32 query rows of one batch. Iterate key tiles of BN=64.
// Maintains online softmax stats (m,l) for BOTH score matrices and two
// unnormalized accumulators O1,O2 (each 32x256).
// out = O1/l1 - lam * O2/l2
// ---------------------------------------------------------------------------
#define ABM 32
#define ABN 64
#define QP  (HD + 1)     // 129, padded pitch for Q/K tiles
#define SP  (ABN + 1)    // 65, padded pitch for score tiles
#define ATHREADS 512

// smem layout (floats)
#define SM_Q1   0
#define SM_Q2   (SM_Q1 + ABM * QP)
#define SM_K1   (SM_Q2 + ABM * QP)
#define SM_K2   (SM_K1 + ABN * QP)
#define SM_V    (SM_K2 + ABN * QP)
#define SM_S1   (SM_V  + ABN * DV)
#define SM_S2   (SM_S1 + ABM * SP)
#define SM_M1   (SM_S2 + ABM * SP)
#define SM_L1   (SM_M1 + ABM)
#define SM_M2   (SM_L1 + ABM)
#define SM_L2   (SM_M2 + ABM)
#define SM_F1   (SM_L2 + ABM)
#define SM_F2   (SM_F1 + ABM)
#define SM_LAM  (SM_F2 + ABM)
#define SM_TOTAL_FLOATS (SM_LAM + 4)
#define SM_TOTAL_BYTES  (SM_TOTAL_FLOATS * 4)

__global__ __launch_bounds__(ATHREADS) void diff_attn_kernel(
    const float* __restrict__ lq1, const float* __restrict__ lq2,
    const float* __restrict__ lk1, const float* __restrict__ lk2,
    float* __restrict__ out)
{
    extern __shared__ float sm[];
    float* Q1s = sm + SM_Q1;
    float* Q2s = sm + SM_Q2;
    float* K1s = sm + SM_K1;
    float* K2s = sm + SM_K2;
    float* Vs  = sm + SM_V;
    float* S1s = sm + SM_S1;
    float* S2s = sm + SM_S2;
    float* mr1 = sm + SM_M1;
    float* lr1 = sm + SM_L1;
    float* mr2 = sm + SM_M2;
    float* lr2 = sm + SM_L2;
    float* fr1 = sm + SM_F1;
    float* fr2 = sm + SM_F2;
    float* lamp = sm + SM_LAM;

    const int tid = threadIdx.x;
    const int b   = blockIdx.y;
    const int q0  = blockIdx.x * ABM;
    const float scale = 0.08838834764831845f;  // HD^-0.5

    // --- lambda scalar (redundant per CTA, cheap) ---
    if (tid < 32) {
        float s1 = 0.f, s2 = 0.f;
        for (int i = tid; i < HD; i += 32) {
            s1 += lq1[i] * lk1[i];
            s2 += lq2[i] * lk2[i];
        }
#pragma unroll
        for (int o = 16; o; o >>= 1) {
            s1 += __shfl_xor_sync(0xffffffffu, s1, o);
            s2 += __shfl_xor_sync(0xffffffffu, s2, o);
        }
        if (tid == 0) {
            double li = 0.8 - 0.6 * exp(-3.6);  // lambda_init, DEPTH=12
            lamp[0] = __expf(s1) + __expf(s2) + (float)li;
        }
    }
    if (tid < ABM) {
        mr1[tid] = -INFINITY; mr2[tid] = -INFINITY;
        lr1[tid] = 0.f;       lr2[tid] = 0.f;
    }

    // --- load Q tile (pre-scaled) ---
    for (int idx = tid; idx < ABM * DV; idx += ATHREADS) {
        int r = idx >> 8, c = idx & 255;
        float v = g_Q[(size_t)(b * SEQ + q0 + r) * DV + c] * scale;
        if (c < HD) Q1s[r * QP + c] = v;
        else        Q2s[r * QP + (c - HD)] = v;
    }

    // --- accumulators: thread owns 2 rows x 8 cols in O1 and O2 ---
    const int rp = tid & 15;          // row-pair index
    const int cg = tid >> 4;          // 0..31 column group
    const int r0 = rp * 2, r1 = rp * 2 + 1;
    const int c0 = cg * 8;
    float O1[2][8], O2[2][8];
#pragma unroll
    for (int i = 0; i < 2; i++)
#pragma unroll
        for (int j = 0; j < 8; j++) { O1[i][j] = 0.f; O2[i][j] = 0.f; }

    // --- score mapping: 256 threads -> S1, 256 -> S2; each 2 rows x 4 cols ---
    const int sg   = tid & 255;
    const int sr0  = (sg & 15) * 2;
    const int sc0  = (sg >> 4) * 4;
    const bool use2 = (tid >= 256);

    __syncthreads();

    for (int j0 = 0; j0 < SEQ; j0 += ABN) {
        // load K, V tiles
        for (int idx = tid; idx < ABN * DV; idx += ATHREADS) {
            int r = idx >> 8, c = idx & 255;
            size_t g = (size_t)(b * SEQ + j0 + r) * DV + c;
            float kv = g_K[g];
            if (c < HD) K1s[r * QP + c] = kv;
            else        K2s[r * QP + (c - HD)] = kv;
            Vs[r * DV + c] = g_V[g];
        }
        __syncthreads();

        // scores: S = Q · K^T (Q pre-scaled)
        {
            const float* Qb = use2 ? Q2s : Q1s;
            const float* Kb = use2 ? K2s : K1s;
            float*       Sb = use2 ? S2s : S1s;
            float acc[2][4];
#pragma unroll
            for (int i = 0; i < 2; i++)
#pragma unroll
                for (int j = 0; j < 4; j++) acc[i][j] = 0.f;
#pragma unroll 8
            for (int k = 0; k < HD; k++) {
                float qa = Qb[sr0 * QP + k];
                float qb = Qb[(sr0 + 1) * QP + k];
#pragma unroll
                for (int j = 0; j < 4; j++) {
                    float kv = Kb[(sc0 + j) * QP + k];
                    acc[0][j] += qa * kv;
                    acc[1][j] += qb * kv;
                }
            }
#pragma unroll
            for (int i = 0; i < 2; i++)
#pragma unroll
                for (int j = 0; j < 4; j++)
                    Sb[(sr0 + i) * SP + sc0 + j] = acc[i][j];
        }
        __syncthreads();

        // online softmax bookkeeping: 64 threads, one (row, matrix) each
        if (tid < 64) {
            const int row = tid & 31;
            float* Sb = (tid < 32) ? S1s : S2s;
            float* mr = (tid < 32) ? mr1 : mr2;
            float* lr = (tid < 32) ? lr1 : lr2;
            float* fr = (tid < 32) ? fr1 : fr2;
            float mold = mr[row];
            float tmax = -INFINITY;
#pragma unroll 8
            for (int c = 0; c < ABN; c++) tmax = fmaxf(tmax, Sb[row * SP + c]);
            float mnew = fmaxf(mold, tmax);
            float sum = 0.f;
#pragma unroll 8
            for (int c = 0; c < ABN; c++) {
                float e = __expf(Sb[row * SP + c] - mnew);
                Sb[row * SP + c] = e;
                sum += e;
            }
            float f = __expf(mold - mnew);  // 0 on first tile
            mr[row] = mnew;
            lr[row] = lr[row] * f + sum;
            fr[row] = f;
        }
        __syncthreads();

        // PV accumulate with rescale
        {
            float f1a = fr1[r0], f1b = fr1[r1];
            float f2a = fr2[r0], f2b = fr2[r1];
#pragma unroll
            for (int j = 0; j < 8; j++) {
                O1[0][j] *= f1a; O1[1][j] *= f1b;
                O2[0][j] *= f2a; O2[1][j] *= f2b;
            }
#pragma unroll 4
            for (int k = 0; k < ABN; k++) {
                float p1a = S1s[r0 * SP + k], p1b = S1s[r1 * SP + k];
                float p2a = S2s[r0 * SP + k], p2b = S2s[r1 * SP + k];
                const float* vr = &Vs[k * DV + c0];
#pragma unroll
                for (int j = 0; j < 8; j++) {
                    float v = vr[j];
                    O1[0][j] += p1a * v;
                    O1[1][j] += p1b * v;
                    O2[0][j] += p2a * v;
                    O2[1][j] += p2b * v;
                }
            }
        }
        __syncthreads();
    }

    // epilogue
    const float lam  = lamp[0];
    const float i1a = 1.f / lr1[r0], i1b = 1.f / lr1[r1];
    const float i2a = 1.f / lr2[r0], i2b = 1.f / lr2[r1];
    const size_t base = (size_t)(b * SEQ + q0) * DV;
#pragma unroll
    for (int j = 0; j < 8; j++) {
        out[base + (size_t)r0 * DV + c0 + j] = O1[0][j] * i1a - lam * O2[0][j] * i2a;
        out[base + (size_t)r1 * DV + c0 + j] = O1[1][j] * i1b - lam * O2[1][j] * i2b;
    }
}

// ---------------------------------------------------------------------------
// Launch
// ---------------------------------------------------------------------------
extern "C" void kernel_launch(void* const* d_in, const int* in_sizes, int n_in,
                              void* d_out, int out_size)
{
    const float* x   = (const float*)d_in[0];
    const float* WQ  = (const float*)d_in[1];
    const float* WK  = (const float*)d_in[2];
    const float* WV  = (const float*)d_in[3];
    const float* lq1 = (const float*)d_in[4];
    const float* lq2 = (const float*)d_in[5];
    const float* lk1 = (const float*)d_in[6];
    const float* lk2 = (const float*)d_in[7];
    float* out = (float*)d_out;

    // projections: grid (N/128=2, M/128=128, 3)
    dim3 pgrid(DV / 128, MROWS / 128, 3);
    proj_gemm_kernel<<<pgrid, 256>>>(x, WQ, WK, WV);

    // attention
    cudaFuncSetAttribute(diff_attn_kernel,
                         cudaFuncAttributeMaxDynamicSharedMemorySize,
                         SM_TOTAL_BYTES);
    dim3 agrid(SEQ / ABM, BATCH);
    diff_attn_kernel<<<agrid, ATHREADS, SM_TOTAL_BYTES>>>(lq1, lq2, lk1, lk2, out);
}

// round 3
// speedup vs baseline: 1.6587x; 1.6587x over previous
#include <cuda_runtime.h>
#include <math.h>
#include <stdint.h>

// ---------------------------------------------------------------------------
// Problem constants
// ---------------------------------------------------------------------------
#define BATCH 4
#define SEQ   4096
#define DMODEL 2048
#define HD    128
#define DV    256
#define MROWS (BATCH*SEQ)

// Scratch for projected Q,K,V
__device__ float g_Q[MROWS * DV];
__device__ float g_K[MROWS * DV];
__device__ float g_V[MROWS * DV];

// ---------------------------------------------------------------------------
// tf32 mma.sync helpers (family-common PTX; NO sm_103a-only features)
// ---------------------------------------------------------------------------
__device__ __forceinline__ void tf32_split(float x, uint32_t& hi, uint32_t& lo) {
    uint32_t h;
    asm("cvt.rna.tf32.f32 %0, %1;" : "=r"(h) : "f"(x));
    hi = h;
    lo = __float_as_uint(x - __uint_as_float(h));
}

__device__ __forceinline__ void mma_m16n8k8(float c[4], const uint32_t a[4], const uint32_t b[2]) {
    asm volatile(
        "mma.sync.aligned.m16n8k8.row.col.f32.tf32.tf32.f32 "
        "{%0,%1,%2,%3}, {%4,%5,%6,%7}, {%8,%9}, {%0,%1,%2,%3};"
        : "+f"(c[0]), "+f"(c[1]), "+f"(c[2]), "+f"(c[3])
        : "r"(a[0]), "r"(a[1]), "r"(a[2]), "r"(a[3]), "r"(b[0]), "r"(b[1]));
}

// 3-term split: c += A*B at ~fp32 accuracy (residual ~2^-22)
__device__ __forceinline__ void mma3(float c[4], const uint32_t ah[4], const uint32_t al[4],
                                     const uint32_t bh[2], const uint32_t bl[2]) {
    mma_m16n8k8(c, ah, bh);
    mma_m16n8k8(c, al, bh);
    mma_m16n8k8(c, ah, bl);
}

// ---------------------------------------------------------------------------
// Kernel 1: projection GEMM, C = x @ W  (M=16384, N=256, K=2048), 3 weights.
// CTA tile 128x128, 8 warps, warp tile 32x64, BK=32.
// Smem pitches: A pitch 36 (4*gid+tig conflict-free), B pitch 136 (8*tig+gid).
// ---------------------------------------------------------------------------
#define PAP 36
#define PBP 136

__global__ __launch_bounds__(256, 2) void proj_mma_kernel(
    const float* __restrict__ x, const float* __restrict__ WQ,
    const float* __restrict__ WK, const float* __restrict__ WV)
{
    __shared__ float As[128 * PAP];
    __shared__ float Bs[32 * PBP];

    const int tid = threadIdx.x;
    const int w   = tid >> 5, l = tid & 31;
    const int gid = l >> 2,  tig = l & 3;
    const int wr  = w >> 1,  wc  = w & 1;
    const int m0c = blockIdx.x * 128;
    const int n0c = blockIdx.y * 128;
    const float* __restrict__ W = (blockIdx.z == 0) ? WQ : (blockIdx.z == 1) ? WK : WV;
    float* __restrict__ C = (blockIdx.z == 0) ? g_Q : (blockIdx.z == 1) ? g_K : g_V;

    float acc[2][8][4];
#pragma unroll
    for (int mb = 0; mb < 2; mb++)
#pragma unroll
        for (int nb = 0; nb < 8; nb++)
#pragma unroll
            for (int i = 0; i < 4; i++) acc[mb][nb][i] = 0.f;

    for (int k0 = 0; k0 < DMODEL; k0 += 32) {
        __syncthreads();
        // stage A: 128 rows x 32 cols
#pragma unroll
        for (int p = 0; p < 4; p++) {
            int row = p * 32 + (tid >> 3);
            int f4  = (tid & 7) * 4;
            float4 v = *(const float4*)&x[(size_t)(m0c + row) * DMODEL + k0 + f4];
            *(float4*)&As[row * PAP + f4] = v;
        }
        // stage B: 32 rows x 128 cols from W[k][n]
#pragma unroll
        for (int p = 0; p < 4; p++) {
            int kr = p * 8 + (tid >> 5);
            int f4 = (tid & 31) * 4;
            float4 v = *(const float4*)&W[(size_t)(k0 + kr) * DV + n0c + f4];
            *(float4*)&Bs[kr * PBP + f4] = v;
        }
        __syncthreads();

#pragma unroll
        for (int ks = 0; ks < 4; ks++) {
            uint32_t ah[2][4], al[2][4];
#pragma unroll
            for (int mb = 0; mb < 2; mb++) {
                const float* ap = &As[(wr * 32 + mb * 16 + gid) * PAP + ks * 8 + tig];
                tf32_split(ap[0],           ah[mb][0], al[mb][0]);
                tf32_split(ap[8 * PAP],     ah[mb][1], al[mb][1]);
                tf32_split(ap[4],           ah[mb][2], al[mb][2]);
                tf32_split(ap[8 * PAP + 4], ah[mb][3], al[mb][3]);
            }
#pragma unroll
            for (int nb = 0; nb < 8; nb++) {
                const float* bp = &Bs[(ks * 8 + tig) * PBP + wc * 64 + nb * 8 + gid];
                uint32_t bh[2], bl[2];
                tf32_split(bp[0],       bh[0], bl[0]);
                tf32_split(bp[4 * PBP], bh[1], bl[1]);
                mma3(acc[0][nb], ah[0], al[0], bh, bl);
                mma3(acc[1][nb], ah[1], al[1], bh, bl);
            }
        }
    }

#pragma unroll
    for (int mb = 0; mb < 2; mb++) {
        int r0 = m0c + wr * 32 + mb * 16 + gid;
#pragma unroll
        for (int nb = 0; nb < 8; nb++) {
            int cc = n0c + wc * 64 + nb * 8 + 2 * tig;
            *(float2*)&C[(size_t)r0 * DV + cc]       = make_float2(acc[mb][nb][0], acc[mb][nb][1]);
            *(float2*)&C[(size_t)(r0 + 8) * DV + cc] = make_float2(acc[mb][nb][2], acc[mb][nb][3]);
        }
    }
}

// ---------------------------------------------------------------------------
// Kernel 2: flash differential attention on tf32 mma.sync with 3x split.
// BM=64 q rows/CTA, BN=32 keys/tile, 512 threads (16 warps).
// Warps 0-7: score mat 1 / O1; warps 8-15: mat 2 / O2.
// ---------------------------------------------------------------------------
#define ABM 64
#define ABN 32
#define ATHR 512
#define QPITCH 132
#define VPITCH 264
#define SPITCH 68

// float offsets in dynamic smem
#define SQ1 0
#define SQ2 (SQ1 + ABM * QPITCH)
#define SK1 (SQ2 + ABM * QPITCH)
#define SK2 (SK1 + ABN * QPITCH)
#define SV  (SK2 + ABN * QPITCH)
#define SS1 (SV + ABN * VPITCH)
#define SS2 (SS1 + ABM * SPITCH)
#define SMR (SS2 + ABM * SPITCH)
#define SLR (SMR + 2 * ABM)
#define SFR (SLR + 2 * ABM)
#define SLAM (SFR + 2 * ABM)
#define ATOT (SLAM + 4)
#define ATOT_BYTES (ATOT * 4)

__global__ __launch_bounds__(ATHR, 1) void diff_attn_mma(
    const float* __restrict__ lq1, const float* __restrict__ lq2,
    const float* __restrict__ lk1, const float* __restrict__ lk2,
    float* __restrict__ out)
{
    extern __shared__ float sm[];
    const int tid = threadIdx.x;
    const int w   = tid >> 5, l = tid & 31;
    const int gid = l >> 2,  tig = l & 3;
    const int b   = blockIdx.y;
    const int q0  = blockIdx.x * ABM;
    const float scale = 0.08838834764831845f;  // HD^-0.5

    // lambda scalar
    if (tid < 32) {
        float s1 = 0.f, s2 = 0.f;
        for (int i = l; i < HD; i += 32) {
            s1 += lq1[i] * lk1[i];
            s2 += lq2[i] * lk2[i];
        }
#pragma unroll
        for (int o = 16; o; o >>= 1) {
            s1 += __shfl_xor_sync(0xffffffffu, s1, o);
            s2 += __shfl_xor_sync(0xffffffffu, s2, o);
        }
        if (l == 0) {
            double li = 0.8 - 0.6 * exp(-3.6);  // lambda_init, DEPTH=12
            sm[SLAM] = __expf(s1) + __expf(s2) + (float)li;
        }
    }
    if (tid < 128) { sm[SMR + tid] = -INFINITY; sm[SLR + tid] = 0.f; }

    // load Q (pre-scaled) into Q1/Q2 tiles
    for (int idx = tid; idx < ABM * 64; idx += ATHR) {
        int r = idx >> 6, f4 = idx & 63;
        float4 v = *(const float4*)&g_Q[(size_t)(b * SEQ + q0 + r) * DV + f4 * 4];
        v.x *= scale; v.y *= scale; v.z *= scale; v.w *= scale;
        if (f4 < 32) *(float4*)&sm[SQ1 + r * QPITCH + f4 * 4] = v;
        else         *(float4*)&sm[SQ2 + r * QPITCH + (f4 - 32) * 4] = v;
    }

    // warp roles
    const int mat = w >> 3;        // 0: (Q1,K1,S1,O1)  1: (Q2,K2,S2,O2)
    const int wl  = w & 7;
    const int smb = wl >> 1, snp = wl & 1;   // QK: rows smb*16, cols snp*16
    const int pm  = wl & 3,  ch  = wl >> 2;  // PV: rows pm*16, cols ch*128
    const int matQ = mat ? SQ2 : SQ1;
    const int matK = mat ? SK2 : SK1;
    const int matS = mat ? SS2 : SS1;

    float O[16][4];
#pragma unroll
    for (int nt = 0; nt < 16; nt++)
#pragma unroll
        for (int i = 0; i < 4; i++) O[nt][i] = 0.f;

    for (int j0 = 0; j0 < SEQ; j0 += ABN) {
        __syncthreads();   // prev PV / KV consumers done
        // load K,V tile (32 rows x 256)
        for (int idx = tid; idx < ABN * 64; idx += ATHR) {
            int r = idx >> 6, f4 = idx & 63;
            size_t g = (size_t)(b * SEQ + j0 + r) * DV + f4 * 4;
            float4 kv = *(const float4*)&g_K[g];
            float4 vv = *(const float4*)&g_V[g];
            if (f4 < 32) *(float4*)&sm[SK1 + r * QPITCH + f4 * 4] = kv;
            else         *(float4*)&sm[SK2 + r * QPITCH + (f4 - 32) * 4] = kv;
            *(float4*)&sm[SV + r * VPITCH + f4 * 4] = vv;
        }
        __syncthreads();

        // QK^T -> S (each warp: 16 rows x 16 cols = 2 mma n-blocks)
        {
            float c[2][4] = {{0.f,0.f,0.f,0.f},{0.f,0.f,0.f,0.f}};
#pragma unroll
            for (int ks = 0; ks < 16; ks++) {
                const float* ap = &sm[matQ + (smb * 16 + gid) * QPITCH + ks * 8 + tig];
                uint32_t ah[4], al[4];
                tf32_split(ap[0],              ah[0], al[0]);
                tf32_split(ap[8 * QPITCH],     ah[1], al[1]);
                tf32_split(ap[4],              ah[2], al[2]);
                tf32_split(ap[8 * QPITCH + 4], ah[3], al[3]);
#pragma unroll
                for (int nb = 0; nb < 2; nb++) {
                    const float* bp = &sm[matK + (snp * 16 + nb * 8 + gid) * QPITCH + ks * 8 + tig];
                    uint32_t bh[2], bl[2];
                    tf32_split(bp[0], bh[0], bl[0]);
                    tf32_split(bp[4], bh[1], bl[1]);
                    mma3(c[nb], ah, al, bh, bl);
                }
            }
#pragma unroll
            for (int nb = 0; nb < 2; nb++) {
                int rr = smb * 16 + gid;
                int cc = snp * 16 + nb * 8 + 2 * tig;
                sm[matS + rr * SPITCH + cc]           = c[nb][0];
                sm[matS + rr * SPITCH + cc + 1]       = c[nb][1];
                sm[matS + (rr + 8) * SPITCH + cc]     = c[nb][2];
                sm[matS + (rr + 8) * SPITCH + cc + 1] = c[nb][3];
            }
        }
        __syncthreads();

        // online softmax: 4 lanes per (mat,row), 8 cols each
        {
            int task = tid >> 2, sub = tid & 3;
            int smat = task >> 6, srow = task & 63;
            float* Srow = &sm[(smat ? SS2 : SS1) + srow * SPITCH + sub * 8];
            float mold = sm[SMR + smat * 64 + srow];
            float v[8];
            float tmax = -INFINITY;
#pragma unroll
            for (int i = 0; i < 8; i++) { v[i] = Srow[i]; tmax = fmaxf(tmax, v[i]); }
            tmax = fmaxf(tmax, __shfl_xor_sync(0xffffffffu, tmax, 1));
            tmax = fmaxf(tmax, __shfl_xor_sync(0xffffffffu, tmax, 2));
            float mnew = fmaxf(mold, tmax);
            float sum = 0.f;
#pragma unroll
            for (int i = 0; i < 8; i++) {
                float e = __expf(v[i] - mnew);
                Srow[i] = e;
                sum += e;
            }
            sum += __shfl_xor_sync(0xffffffffu, sum, 1);
            sum += __shfl_xor_sync(0xffffffffu, sum, 2);
            if (sub == 0) {
                float f = __expf(mold - mnew);
                sm[SMR + smat * 64 + srow] = mnew;
                sm[SLR + smat * 64 + srow] = sm[SLR + smat * 64 + srow] * f + sum;
                sm[SFR + smat * 64 + srow] = f;
            }
        }
        __syncthreads();

        // PV accumulate with rescale (each warp: 16 rows x 128 cols of O{mat})
        {
            float fa = sm[SFR + mat * 64 + pm * 16 + gid];
            float fb = sm[SFR + mat * 64 + pm * 16 + gid + 8];
#pragma unroll
            for (int nt = 0; nt < 16; nt++) {
                O[nt][0] *= fa; O[nt][1] *= fa; O[nt][2] *= fb; O[nt][3] *= fb;
            }
#pragma unroll
            for (int kk = 0; kk < 4; kk++) {
                const float* ap = &sm[matS + (pm * 16 + gid) * SPITCH + kk * 8 + tig];
                uint32_t ah[4], al[4];
                tf32_split(ap[0],              ah[0], al[0]);
                tf32_split(ap[8 * SPITCH],     ah[1], al[1]);
                tf32_split(ap[4],              ah[2], al[2]);
                tf32_split(ap[8 * SPITCH + 4], ah[3], al[3]);
#pragma unroll
                for (int nt = 0; nt < 16; nt++) {
                    const float* bp = &sm[SV + (kk * 8 + tig) * VPITCH + ch * 128 + nt * 8 + gid];
                    uint32_t bh[2], bl[2];
                    tf32_split(bp[0],          bh[0], bl[0]);
                    tf32_split(bp[4 * VPITCH], bh[1], bl[1]);
                    mma3(O[nt], ah, al, bh, bl);
                }
            }
        }
    }
    __syncthreads();

    // epilogue: out = O1/l1 - lam*O2/l2 (combine via smem scratch over Q tiles)
    const float lam = sm[SLAM];
    const int ra = pm * 16 + gid, rb = ra + 8;
    if (mat == 1) {
        float s2a = lam / sm[SLR + 64 + ra];
        float s2b = lam / sm[SLR + 64 + rb];
#pragma unroll
        for (int nt = 0; nt < 16; nt++) {
            int cc = ch * 128 + nt * 8 + 2 * tig;
            sm[SQ1 + ra * VPITCH + cc]     = O[nt][0] * s2a;
            sm[SQ1 + ra * VPITCH + cc + 1] = O[nt][1] * s2a;
            sm[SQ1 + rb * VPITCH + cc]     = O[nt][2] * s2b;
            sm[SQ1 + rb * VPITCH + cc + 1] = O[nt][3] * s2b;
        }
    }
    __syncthreads();
    if (mat == 0) {
        float i1a = 1.f / sm[SLR + ra];
        float i1b = 1.f / sm[SLR + rb];
        size_t basea = (size_t)(b * SEQ + q0 + ra) * DV;
        size_t baseb = (size_t)(b * SEQ + q0 + rb) * DV;
#pragma unroll
        for (int nt = 0; nt < 16; nt++) {
            int cc = ch * 128 + nt * 8 + 2 * tig;
            float2 o;
            o.x = O[nt][0] * i1a - sm[SQ1 + ra * VPITCH + cc];
            o.y = O[nt][1] * i1a - sm[SQ1 + ra * VPITCH + cc + 1];
            *(float2*)&out[basea + cc] = o;
            o.x = O[nt][2] * i1b - sm[SQ1 + rb * VPITCH + cc];
            o.y = O[nt][3] * i1b - sm[SQ1 + rb * VPITCH + cc + 1];
            *(float2*)&out[baseb + cc] = o;
        }
    }
}

// ---------------------------------------------------------------------------
// Launch
// ---------------------------------------------------------------------------
extern "C" void kernel_launch(void* const* d_in, const int* in_sizes, int n_in,
                              void* d_out, int out_size)
{
    const float* x   = (const float*)d_in[0];
    const float* WQ  = (const float*)d_in[1];
    const float* WK  = (const float*)d_in[2];
    const float* WV  = (const float*)d_in[3];
    const float* lq1 = (const float*)d_in[4];
    const float* lq2 = (const float*)d_in[5];
    const float* lk1 = (const float*)d_in[6];
    const float* lk2 = (const float*)d_in[7];
    float* out = (float*)d_out;

    // projections: grid (M/128, N/128, 3)
    dim3 pgrid(MROWS / 128, DV / 128, 3);
    proj_mma_kernel<<<pgrid, 256>>>(x, WQ, WK, WV);

    // attention
    cudaFuncSetAttribute(diff_attn_mma,
                         cudaFuncAttributeMaxDynamicSharedMemorySize, ATOT_BYTES);
    dim3 agrid(SEQ / ABM, BATCH);
    diff_attn_mma<<<agrid, ATHR, ATOT_BYTES>>>(lq1, lq2, lk1, lk2, out);
}